// round 2
// baseline (speedup 1.0000x reference)
#include <cuda_runtime.h>
#include <cstdint>
#include <cstddef>

// ---------------------------------------------------------------------------
// LinAngularAttention, fp32 CUDA-core implementation (Round 2 resubmit: Round
// 1 bench died on container acquisition, not on the kernel).
// Shapes fixed by the problem:
//   B=8, N=4096, C=384, heads=8, head_dim=48, dconv kernel 9.
// Pipeline:
//   K0: zero attn accumulator
//   K1: fused dual GEMM  qk = x@Wqk^T (sign only kept), v = x@Wv^T
//   K2: attn[bh] = sign_qk^T @ v   (per (b,h) 48x48, atomic partial sums)
//   K3: out = normalize(0.5 v + (1/pi) qk@attn) + dconv(v)  -> pre [B,N,C]
//   K4: out = pre @ Wproj^T + b
// Precision note: sign(qk/||qk||) == sign(qk), but the sign() is a hard
// nonlinearity -> qk GEMM must stay fp32 with low accumulation error
// (chunked dual accumulation). Everything else is linear-error-tolerant.
// ---------------------------------------------------------------------------

#define BATCH 8
#define SEQ   4096
#define CH    384
#define NH    8
#define HD    48
#define TOK   (BATCH*SEQ)           // 32768
#define KS9   9
#define INV_PI 0.31830988618379067f

// persistent scratch (device globals: no allocation allowed)
__device__ float        g_v  [(size_t)BATCH*NH*SEQ*HD];   // [b,h,n,d]  50 MB
__device__ signed char  g_qs [(size_t)BATCH*NH*SEQ*HD];   // sign(qk)   12.6 MB
__device__ float        g_attn[BATCH*NH*HD*HD];           // [bh,d,e]
__device__ float        g_pre[(size_t)TOK*CH];            // [b,n,c]    50 MB

typedef unsigned long long u64;

// ---- packed fp32x2 helpers (Blackwell FFMA2 path; ptxas never emits these
//      from C++, so inline PTX) ----------------------------------------------
__device__ __forceinline__ u64 pk2(float lo, float hi) {
    u64 r; asm("mov.b64 %0,{%1,%2};" : "=l"(r) : "f"(lo), "f"(hi)); return r;
}
__device__ __forceinline__ void upk2(u64 v, float& lo, float& hi) {
    asm("mov.b64 {%0,%1},%2;" : "=f"(lo), "=f"(hi) : "l"(v));
}
__device__ __forceinline__ u64 ffma2(u64 a, u64 b, u64 c) {
    u64 d; asm("fma.rn.f32x2 %0,%1,%2,%3;" : "=l"(d) : "l"(a), "l"(b), "l"(c)); return d;
}
__device__ __forceinline__ u64 fadd2(u64 a, u64 b) {
    u64 d; asm("add.rn.f32x2 %0,%1,%2;" : "=l"(d) : "l"(a), "l"(b)); return d;
}

// ---------------------------------------------------------------------------
// K0: zero attn accumulator (graph replays re-run everything, so no statics)
// ---------------------------------------------------------------------------
__global__ void k_zero_attn() {
    int i = blockIdx.x * blockDim.x + threadIdx.x;
    if (i < BATCH*NH*HD*HD) g_attn[i] = 0.0f;
}

// ---------------------------------------------------------------------------
// K1: fused qk/v GEMM.  Tile 64(M) x 64(N) x 32(K), 256 threads, per-thread
// 4x4 per matrix with N packed in f32x2 pairs.  qk uses chunked accumulation
// (fold every K-tile) to halve fp32 rounding noise ahead of the sign().
// ---------------------------------------------------------------------------
#define BM1 64
#define BN1 64
#define BK1 32

__global__ __launch_bounds__(256)
void k_qkv(const float* __restrict__ x,
           const float* __restrict__ wqk,
           const float* __restrict__ wv) {
    __shared__ float As[BM1][BK1+1];                    // [m][k]
    __shared__ __align__(16) float Bq[BK1][BN1+2];      // [k][n], row = 264 B (8-mult)
    __shared__ __align__(16) float Bv[BK1][BN1+2];

    const int tid = threadIdx.x;
    const int tx = tid & 15;        // col group: cols tx*4 .. tx*4+3
    const int ty = tid >> 4;        // row group: rows ty*4 .. ty*4+3
    const int m0 = blockIdx.y * BM1;
    const int n0 = blockIdx.x * BN1;

    u64 accq[4][2], accqc[4][2], accv[4][2];
    #pragma unroll
    for (int i = 0; i < 4; i++)
        #pragma unroll
        for (int j = 0; j < 2; j++) { accq[i][j] = 0ull; accqc[i][j] = 0ull; accv[i][j] = 0ull; }

    for (int k0 = 0; k0 < CH; k0 += BK1) {
        #pragma unroll
        for (int l = tid; l < BM1*BK1; l += 256) {
            int r = l >> 5, c = l & 31;
            As[r][c] = x[(size_t)(m0 + r)*CH + k0 + c];
        }
        #pragma unroll
        for (int l = tid; l < BN1*BK1; l += 256) {
            int r = l >> 5, c = l & 31;
            Bq[c][r] = wqk[(size_t)(n0 + r)*CH + k0 + c];
            Bv[c][r] = wv [(size_t)(n0 + r)*CH + k0 + c];
        }
        __syncthreads();

        #pragma unroll
        for (int kk = 0; kk < BK1; kk++) {
            float a[4];
            u64 bq[2], bv[2];
            #pragma unroll
            for (int i = 0; i < 4; i++) a[i] = As[ty*4 + i][kk];
            #pragma unroll
            for (int j = 0; j < 2; j++) {
                bq[j] = *(const u64*)&Bq[kk][tx*4 + j*2];
                bv[j] = *(const u64*)&Bv[kk][tx*4 + j*2];
            }
            #pragma unroll
            for (int i = 0; i < 4; i++) {
                u64 ap = pk2(a[i], a[i]);
                #pragma unroll
                for (int j = 0; j < 2; j++) {
                    accqc[i][j] = ffma2(ap, bq[j], accqc[i][j]);
                    accv [i][j] = ffma2(ap, bv[j], accv [i][j]);
                }
            }
        }
        __syncthreads();
        // fold chunk (reduces sequential-accumulation error for the sign())
        #pragma unroll
        for (int i = 0; i < 4; i++)
            #pragma unroll
            for (int j = 0; j < 2; j++) {
                accq[i][j] = fadd2(accq[i][j], accqc[i][j]);
                accqc[i][j] = 0ull;
            }
    }

    // epilogue: scatter to [b,h,n,d] layout; qk stored as sign only
    #pragma unroll
    for (int i = 0; i < 4; i++) {
        int m = m0 + ty*4 + i;
        int b = m >> 12;
        int n = m & (SEQ - 1);
        #pragma unroll
        for (int j = 0; j < 2; j++) {
            float qlo, qhi, vlo, vhi;
            upk2(accq[i][j], qlo, qhi);
            upk2(accv[i][j], vlo, vhi);
            int col = n0 + tx*4 + j*2;
            {
                int h = col / HD, d = col % HD;
                size_t idx = ((size_t)(b*NH + h)*SEQ + n)*HD + d;
                g_v[idx]  = vlo;
                g_qs[idx] = (qlo >= 0.0f) ? (signed char)1 : (signed char)-1;
            }
            {
                int c1 = col + 1;
                int h = c1 / HD, d = c1 % HD;
                size_t idx = ((size_t)(b*NH + h)*SEQ + n)*HD + d;
                g_v[idx]  = vhi;
                g_qs[idx] = (qhi >= 0.0f) ? (signed char)1 : (signed char)-1;
            }
        }
    }
}

// ---------------------------------------------------------------------------
// K2: attn[bh,d,e] = sum_n qs[bh,n,d] * v[bh,n,e].
// Grid (64 bh, 8 n-chunks of 512).  256 threads, each owns a 3x3 (d,e) tile.
// ---------------------------------------------------------------------------
__global__ __launch_bounds__(256)
void k_attn() {
    const int bh = blockIdx.x;
    const int nbase = blockIdx.y * 512;
    __shared__ __align__(16) float vs[8][HD];
    __shared__ __align__(16) float qs[8][HD];

    const int tid = threadIdx.x;
    const int dg = tid >> 4;     // 0..15 -> d = dg*3..
    const int eg = tid & 15;     // 0..15 -> e = eg*3..

    const float*       vb = g_v  + (size_t)bh*SEQ*HD;
    const signed char* qb = g_qs + (size_t)bh*SEQ*HD;

    float acc[3][3];
    #pragma unroll
    for (int i = 0; i < 3; i++)
        #pragma unroll
        for (int j = 0; j < 3; j++) acc[i][j] = 0.0f;

    for (int n0 = nbase; n0 < nbase + 512; n0 += 8) {
        // 8*48 = 384 elements; widen qs fill via char4 (96 per 4-pack)
        #pragma unroll
        for (int l = tid; l < 8*HD; l += 256) {
            vs[l / HD][l % HD] = vb[(size_t)n0*HD + l];
        }
        if (tid < 96) {
            char4 c4 = *(const char4*)(qb + (size_t)n0*HD + tid*4);
            int base = tid*4;
            qs[(base    ) / HD][(base    ) % HD] = (float)c4.x;
            qs[(base + 1) / HD][(base + 1) % HD] = (float)c4.y;
            qs[(base + 2) / HD][(base + 2) % HD] = (float)c4.z;
            qs[(base + 3) / HD][(base + 3) % HD] = (float)c4.w;
        }
        __syncthreads();
        #pragma unroll
        for (int r = 0; r < 8; r++) {
            float q0 = qs[r][dg*3 + 0], q1 = qs[r][dg*3 + 1], q2 = qs[r][dg*3 + 2];
            float v0 = vs[r][eg*3 + 0], v1 = vs[r][eg*3 + 1], v2 = vs[r][eg*3 + 2];
            acc[0][0] += q0*v0; acc[0][1] += q0*v1; acc[0][2] += q0*v2;
            acc[1][0] += q1*v0; acc[1][1] += q1*v1; acc[1][2] += q1*v2;
            acc[2][0] += q2*v0; acc[2][1] += q2*v1; acc[2][2] += q2*v2;
        }
        __syncthreads();
    }
    #pragma unroll
    for (int i = 0; i < 3; i++)
        #pragma unroll
        for (int j = 0; j < 3; j++)
            atomicAdd(&g_attn[(size_t)bh*HD*HD + (dg*3 + i)*HD + (eg*3 + j)], acc[i][j]);
}

// ---------------------------------------------------------------------------
// K3: per (b,h), 64-token chunk:
//   t = 0.5 v + (1/pi) qs@attn ; o = t/||t|| + dconv(v) ; scatter to [b,n,c]
// Block 384 threads = (e in 0..47) x (8 tokens in flight).
// ---------------------------------------------------------------------------
__global__ __launch_bounds__(384)
void k_out(const float* __restrict__ dcw) {
    const int bh = blockIdx.x;
    const int h  = bh & 7;
    const int b  = bh >> 3;
    const int n0 = blockIdx.y * 64;

    __shared__ __align__(16) float attn_t[HD][HD];   // [e][d]  (transposed)
    __shared__ __align__(16) float vt[72][HD];       // rows n0-4 .. n0+67
    __shared__ __align__(16) float qt[64][HD];
    __shared__ float ts[8][HD];
    __shared__ float rn[8];
    __shared__ float dw[KS9];

    const int tid = threadIdx.x;
    const float*       vb = g_v  + (size_t)bh*SEQ*HD;
    const signed char* qb = g_qs + (size_t)bh*SEQ*HD;

    for (int l = tid; l < HD*HD; l += 384) {
        int d = l / HD, e = l % HD;
        attn_t[e][d] = g_attn[(size_t)bh*HD*HD + l];
    }
    if (tid < KS9) dw[tid] = dcw[h*KS9 + tid];
    for (int l = tid; l < 72*HD; l += 384) {
        int r = l / HD, c = l % HD;
        int n = n0 - 4 + r;
        vt[r][c] = (n >= 0 && n < SEQ) ? vb[(size_t)n*HD + c] : 0.0f;
    }
    for (int l = tid; l < 64*HD; l += 384) {
        qt[l / HD][l % HD] = (float)qb[(size_t)n0*HD + l];
    }
    __syncthreads();

    const int e  = tid % HD;
    const int nl = tid / HD;     // 0..7

    for (int g = 0; g < 8; g++) {
        int tl = g*8 + nl;       // local token 0..63
        const float4* qr = (const float4*)&qt[tl][0];
        const float4* ar = (const float4*)&attn_t[e][0];
        float s = 0.0f;
        #pragma unroll
        for (int q = 0; q < HD/4; q++) {
            float4 qv = qr[q], av = ar[q];
            s += qv.x*av.x; s += qv.y*av.y; s += qv.z*av.z; s += qv.w*av.w;
        }
        float t = 0.5f*vt[tl + 4][e] + INV_PI*s;
        ts[nl][e] = t;
        __syncthreads();
        if (tid < 8) {
            float sm = 0.0f;
            #pragma unroll
            for (int c = 0; c < HD; c++) { float u = ts[tid][c]; sm += u*u; }
            rn[tid] = 1.0f / sqrtf(sm);
        }
        __syncthreads();
        float o = t * rn[nl];
        #pragma unroll
        for (int k = 0; k < KS9; k++) o += dw[k] * vt[tl + k][e];
        int n = n0 + tl;
        g_pre[((size_t)b*SEQ + n)*CH + h*HD + e] = o;
        __syncthreads();
    }
}

// ---------------------------------------------------------------------------
// K4: proj GEMM  out = pre @ Wproj^T + b.  Tile 64x128x32, 256 threads,
// per-thread 4x8 with N packed in f32x2 pairs.
// ---------------------------------------------------------------------------
#define BM4 64
#define BN4 128
#define BK4 32

__global__ __launch_bounds__(256)
void k_proj(const float* __restrict__ wp,
            const float* __restrict__ bias,
            float* __restrict__ out) {
    __shared__ float As[BM4][BK4+1];
    __shared__ __align__(16) float Bs[BK4][BN4+2];   // row = 520 B (8-mult)

    const int tid = threadIdx.x;
    const int tx = tid & 15;       // cols tx*8 .. tx*8+7
    const int ty = tid >> 4;       // rows ty*4 .. ty*4+3
    const int m0 = blockIdx.y * BM4;
    const int n0 = blockIdx.x * BN4;

    u64 acc[4][4];
    #pragma unroll
    for (int i = 0; i < 4; i++)
        #pragma unroll
        for (int j = 0; j < 4; j++) acc[i][j] = 0ull;

    for (int k0 = 0; k0 < CH; k0 += BK4) {
        #pragma unroll
        for (int l = tid; l < BM4*BK4; l += 256) {
            int r = l >> 5, c = l & 31;
            As[r][c] = g_pre[(size_t)(m0 + r)*CH + k0 + c];
        }
        #pragma unroll
        for (int l = tid; l < BN4*BK4; l += 256) {
            int r = l >> 5, c = l & 31;
            Bs[c][r] = wp[(size_t)(n0 + r)*CH + k0 + c];
        }
        __syncthreads();

        #pragma unroll
        for (int kk = 0; kk < BK4; kk++) {
            float a[4];
            u64 bb[4];
            #pragma unroll
            for (int i = 0; i < 4; i++) a[i] = As[ty*4 + i][kk];
            #pragma unroll
            for (int j = 0; j < 4; j++) bb[j] = *(const u64*)&Bs[kk][tx*8 + j*2];
            #pragma unroll
            for (int i = 0; i < 4; i++) {
                u64 ap = pk2(a[i], a[i]);
                #pragma unroll
                for (int j = 0; j < 4; j++) acc[i][j] = ffma2(ap, bb[j], acc[i][j]);
            }
        }
        __syncthreads();
    }

    #pragma unroll
    for (int i = 0; i < 4; i++) {
        int m = m0 + ty*4 + i;
        #pragma unroll
        for (int j = 0; j < 4; j++) {
            int col = n0 + tx*8 + j*2;
            float lo, hi;
            upk2(acc[i][j], lo, hi);
            out[(size_t)m*CH + col]     = lo + bias[col];
            out[(size_t)m*CH + col + 1] = hi + bias[col + 1];
        }
    }
}

// ---------------------------------------------------------------------------
// launch
// ---------------------------------------------------------------------------
extern "C" void kernel_launch(void* const* d_in, const int* in_sizes, int n_in,
                              void* d_out, int out_size) {
    const float* x = nullptr;
    const float* w[3] = {nullptr, nullptr, nullptr};   // w_qk, w_v, w_proj in order
    const float* bproj = nullptr;
    const float* dcw = nullptr;
    int wi = 0;
    for (int i = 0; i < n_in; i++) {
        int sz = in_sizes[i];
        if (sz == TOK*CH)            x = (const float*)d_in[i];
        else if (sz == CH*CH)        { if (wi < 3) w[wi++] = (const float*)d_in[i]; }
        else if (sz == CH)           bproj = (const float*)d_in[i];
        else if (sz == NH*KS9)       dcw = (const float*)d_in[i];
        // size-1 entries (H, W) are unused
    }

    k_zero_attn<<<(BATCH*NH*HD*HD + 255)/256, 256>>>();
    k_qkv <<<dim3(CH/BN1, TOK/BM1), 256>>>(x, w[0], w[1]);
    k_attn<<<dim3(BATCH*NH, 8), 256>>>();
    k_out <<<dim3(BATCH*NH, SEQ/64), 384>>>(dcw);
    k_proj<<<dim3(CH/BN4, TOK/BM4), 256>>>(w[2], bproj, (float*)d_out);
}

// round 4
// speedup vs baseline: 1.3284x; 1.3284x over previous
#include <cuda_runtime.h>
#include <cstdint>
#include <cstddef>

// ---------------------------------------------------------------------------
// LinAngularAttention fp32 (Round 4 = Round 3 resubmit; R3 bench died on
// container acquisition, not the kernel).
//   R2 profile: k_out 368us, L1 94% (bank conflicts on attn_t float4 reads,
//   stride 192B), fma 6.7%. Rewritten: attn column in registers, f32x2 packed
//   dot products, 3 syncs instead of 24, padded rows for conflict-free LDS.
//   k_qkv/k_proj: B-tile rows padded to 16B multiples -> LDS.128 feeds;
//   k_proj widened to 128x128 tile (8x8/thread).
// ---------------------------------------------------------------------------

#define BATCH 8
#define SEQ   4096
#define CH    384
#define NH    8
#define HD    48
#define TOK   (BATCH*SEQ)           // 32768
#define KS9   9
#define INV_PI 0.31830988618379067f

__device__ float        g_v  [(size_t)BATCH*NH*SEQ*HD];   // [b,h,n,d]
__device__ signed char  g_qs [(size_t)BATCH*NH*SEQ*HD];   // sign(qk)
__device__ float        g_attn[BATCH*NH*HD*HD];           // [bh,d,e]
__device__ float        g_pre[(size_t)TOK*CH];            // [b,n,c]

typedef unsigned long long u64;

__device__ __forceinline__ u64 pk2(float lo, float hi) {
    u64 r; asm("mov.b64 %0,{%1,%2};" : "=l"(r) : "f"(lo), "f"(hi)); return r;
}
__device__ __forceinline__ void upk2(u64 v, float& lo, float& hi) {
    asm("mov.b64 {%0,%1},%2;" : "=f"(lo), "=f"(hi) : "l"(v));
}
__device__ __forceinline__ u64 ffma2(u64 a, u64 b, u64 c) {
    u64 d; asm("fma.rn.f32x2 %0,%1,%2,%3;" : "=l"(d) : "l"(a), "l"(b), "l"(c)); return d;
}
__device__ __forceinline__ u64 fadd2(u64 a, u64 b) {
    u64 d; asm("add.rn.f32x2 %0,%1,%2;" : "=l"(d) : "l"(a), "l"(b)); return d;
}

// ---------------------------------------------------------------------------
__global__ void k_zero_attn() {
    int i = blockIdx.x * blockDim.x + threadIdx.x;
    if (i < BATCH*NH*HD*HD) g_attn[i] = 0.0f;
}

// ---------------------------------------------------------------------------
// K1: fused qk/v GEMM. 64x64x32 tile, 256 threads, 4x4 per matrix (f32x2).
// B rows padded to 68 floats (272B = 17*16) so the 4-wide col reads are one
// LDS.128. qk uses chunked dual accumulation (error control before sign()).
// ---------------------------------------------------------------------------
#define BM1 64
#define BN1 64
#define BK1 32

__global__ __launch_bounds__(256)
void k_qkv(const float* __restrict__ x,
           const float* __restrict__ wqk,
           const float* __restrict__ wv) {
    __shared__ float As[BM1][BK1+1];                    // [m][k]
    __shared__ __align__(16) float Bq[BK1][BN1+4];      // [k][n], row 272B
    __shared__ __align__(16) float Bv[BK1][BN1+4];

    const int tid = threadIdx.x;
    const int tx = tid & 15;        // cols tx*4..+3
    const int ty = tid >> 4;        // rows ty*4..+3
    const int m0 = blockIdx.y * BM1;
    const int n0 = blockIdx.x * BN1;

    u64 accq[4][2], accqc[4][2], accv[4][2];
    #pragma unroll
    for (int i = 0; i < 4; i++)
        #pragma unroll
        for (int j = 0; j < 2; j++) { accq[i][j] = 0ull; accqc[i][j] = 0ull; accv[i][j] = 0ull; }

    for (int k0 = 0; k0 < CH; k0 += BK1) {
        #pragma unroll
        for (int l = tid; l < BM1*BK1; l += 256) {
            int r = l >> 5, c = l & 31;
            As[r][c] = x[(size_t)(m0 + r)*CH + k0 + c];
        }
        #pragma unroll
        for (int l = tid; l < BN1*BK1; l += 256) {
            int r = l >> 5, c = l & 31;
            Bq[c][r] = wqk[(size_t)(n0 + r)*CH + k0 + c];
            Bv[c][r] = wv [(size_t)(n0 + r)*CH + k0 + c];
        }
        __syncthreads();

        #pragma unroll
        for (int kk = 0; kk < BK1; kk++) {
            float a[4];
            #pragma unroll
            for (int i = 0; i < 4; i++) a[i] = As[ty*4 + i][kk];
            ulonglong2 bq = *(const ulonglong2*)&Bq[kk][tx*4];
            ulonglong2 bv = *(const ulonglong2*)&Bv[kk][tx*4];
            #pragma unroll
            for (int i = 0; i < 4; i++) {
                u64 ap = pk2(a[i], a[i]);
                accqc[i][0] = ffma2(ap, bq.x, accqc[i][0]);
                accqc[i][1] = ffma2(ap, bq.y, accqc[i][1]);
                accv [i][0] = ffma2(ap, bv.x, accv [i][0]);
                accv [i][1] = ffma2(ap, bv.y, accv [i][1]);
            }
        }
        __syncthreads();
        #pragma unroll
        for (int i = 0; i < 4; i++)
            #pragma unroll
            for (int j = 0; j < 2; j++) {
                accq[i][j] = fadd2(accq[i][j], accqc[i][j]);
                accqc[i][j] = 0ull;
            }
    }

    #pragma unroll
    for (int i = 0; i < 4; i++) {
        int m = m0 + ty*4 + i;
        int b = m >> 12;
        int n = m & (SEQ - 1);
        #pragma unroll
        for (int j = 0; j < 2; j++) {
            float qlo, qhi, vlo, vhi;
            upk2(accq[i][j], qlo, qhi);
            upk2(accv[i][j], vlo, vhi);
            int col = n0 + tx*4 + j*2;
            {
                int h = col / HD, d = col % HD;
                size_t idx = ((size_t)(b*NH + h)*SEQ + n)*HD + d;
                g_v[idx]  = vlo;
                g_qs[idx] = (qlo >= 0.0f) ? (signed char)1 : (signed char)-1;
            }
            {
                int c1 = col + 1;
                int h = c1 / HD, d = c1 % HD;
                size_t idx = ((size_t)(b*NH + h)*SEQ + n)*HD + d;
                g_v[idx]  = vhi;
                g_qs[idx] = (qhi >= 0.0f) ? (signed char)1 : (signed char)-1;
            }
        }
    }
}

// ---------------------------------------------------------------------------
// K2: attn[bh,d,e] = sum_n qs[bh,n,d] * v[bh,n,e].
// ---------------------------------------------------------------------------
__global__ __launch_bounds__(256)
void k_attn() {
    const int bh = blockIdx.x;
    const int nbase = blockIdx.y * 512;
    __shared__ __align__(16) float vs[8][HD];
    __shared__ __align__(16) float qs[8][HD];

    const int tid = threadIdx.x;
    const int dg = tid >> 4;
    const int eg = tid & 15;

    const float*       vb = g_v  + (size_t)bh*SEQ*HD;
    const signed char* qb = g_qs + (size_t)bh*SEQ*HD;

    float acc[3][3];
    #pragma unroll
    for (int i = 0; i < 3; i++)
        #pragma unroll
        for (int j = 0; j < 3; j++) acc[i][j] = 0.0f;

    for (int n0 = nbase; n0 < nbase + 512; n0 += 8) {
        #pragma unroll
        for (int l = tid; l < 8*HD; l += 256) {
            vs[l / HD][l % HD] = vb[(size_t)n0*HD + l];
        }
        if (tid < 96) {
            char4 c4 = *(const char4*)(qb + (size_t)n0*HD + tid*4);
            int base = tid*4;
            qs[(base    ) / HD][(base    ) % HD] = (float)c4.x;
            qs[(base + 1) / HD][(base + 1) % HD] = (float)c4.y;
            qs[(base + 2) / HD][(base + 2) % HD] = (float)c4.z;
            qs[(base + 3) / HD][(base + 3) % HD] = (float)c4.w;
        }
        __syncthreads();
        #pragma unroll
        for (int r = 0; r < 8; r++) {
            float q0 = qs[r][dg*3 + 0], q1 = qs[r][dg*3 + 1], q2 = qs[r][dg*3 + 2];
            float v0 = vs[r][eg*3 + 0], v1 = vs[r][eg*3 + 1], v2 = vs[r][eg*3 + 2];
            acc[0][0] += q0*v0; acc[0][1] += q0*v1; acc[0][2] += q0*v2;
            acc[1][0] += q1*v0; acc[1][1] += q1*v1; acc[1][2] += q1*v2;
            acc[2][0] += q2*v0; acc[2][1] += q2*v1; acc[2][2] += q2*v2;
        }
        __syncthreads();
    }
    #pragma unroll
    for (int i = 0; i < 3; i++)
        #pragma unroll
        for (int j = 0; j < 3; j++)
            atomicAdd(&g_attn[(size_t)bh*HD*HD + (dg*3 + i)*HD + (eg*3 + j)], acc[i][j]);
}

// ---------------------------------------------------------------------------
// K3: per (b,h), 64-token chunk.
//   Phase A: attn column in registers (f32x2 over d); broadcast LDS.128 q.
//   Phase B: 64 threads compute the 64 inverse norms.
//   Phase C: out = t*rn + dconv(v); vt rows padded to 49 floats.
// 3+1 syncs total, zero bank-conflicted inner loads.
// ---------------------------------------------------------------------------
__global__ __launch_bounds__(384)
void k_out(const float* __restrict__ dcw) {
    const int bh = blockIdx.x;
    const int h  = bh & 7;
    const int b  = bh >> 3;
    const int n0 = blockIdx.y * 64;

    __shared__ __align__(16) float vt[72][HD+1];     // rows n0-4..n0+67, pad 49
    __shared__ __align__(16) float qf[64][HD];       // q signs as floats, row 192B
    __shared__ __align__(16) float r3[64*(HD+1)];    // attn staging, then ts
    __shared__ float rn[64];
    __shared__ float dw[KS9];

    const int tid = threadIdx.x;
    const int e  = tid % HD;
    const int nl = tid / HD;     // 0..7

    const float*       vb = g_v  + (size_t)bh*SEQ*HD;
    const signed char* qb = g_qs + (size_t)bh*SEQ*HD;

    // ---- fill ----
    for (int l = tid; l < HD*HD; l += 384)           // attn [d][e] -> staging
        r3[l] = g_attn[(size_t)bh*HD*HD + l];
    if (tid < KS9) dw[tid] = dcw[h*KS9 + tid];
    for (int l = tid; l < 72*HD; l += 384) {
        int r = l / HD, c = l % HD;
        int n = n0 - 4 + r;
        vt[r][c] = (n >= 0 && n < SEQ) ? vb[(size_t)n*HD + c] : 0.0f;
    }
    for (int l = tid; l < 64*HD/4; l += 384) {       // 768 char4 loads
        char4 c4 = *(const char4*)(qb + (size_t)n0*HD + l*4);
        int base = l*4;
        qf[base / HD][base % HD]         = (float)c4.x;
        qf[(base+1) / HD][(base+1) % HD] = (float)c4.y;
        qf[(base+2) / HD][(base+2) % HD] = (float)c4.z;
        qf[(base+3) / HD][(base+3) % HD] = (float)c4.w;
    }
    __syncthreads();

    // ---- pack this thread's attn column into registers (f32x2 over d) ----
    u64 a2[HD/2];
    #pragma unroll
    for (int dp = 0; dp < HD/2; dp++)
        a2[dp] = pk2(r3[(2*dp)*HD + e], r3[(2*dp + 1)*HD + e]);
    __syncthreads();   // before r3 is reused as ts

    // ---- Phase A: t for 8 tokens ----
    float treg[8];
    #pragma unroll
    for (int g = 0; g < 8; g++) {
        int tl = g*8 + nl;
        u64 acc = 0ull;
        const ulonglong2* qr = (const ulonglong2*)&qf[tl][0];
        #pragma unroll
        for (int i = 0; i < HD/4; i++) {
            ulonglong2 qv = qr[i];                   // broadcast LDS.128
            acc = ffma2(qv.x, a2[2*i],     acc);
            acc = ffma2(qv.y, a2[2*i + 1], acc);
        }
        float slo, shi; upk2(acc, slo, shi);
        float t = 0.5f*vt[tl + 4][e] + INV_PI*(slo + shi);
        treg[g] = t;
        r3[tl*(HD+1) + e] = t;                       // ts, row stride 49
    }
    __syncthreads();

    // ---- Phase B: 64 norms ----
    if (tid < 64) {
        float sm = 0.0f;
        #pragma unroll
        for (int c = 0; c < HD; c++) { float u = r3[tid*(HD+1) + c]; sm += u*u; }
        rn[tid] = rsqrtf(sm);
    }
    __syncthreads();

    // ---- Phase C: normalize + dconv + store ----
    #pragma unroll
    for (int g = 0; g < 8; g++) {
        int tl = g*8 + nl;
        float o = treg[g] * rn[tl];
        #pragma unroll
        for (int k = 0; k < KS9; k++) o += dw[k] * vt[tl + k][e];
        int n = n0 + tl;
        g_pre[((size_t)b*SEQ + n)*CH + h*HD + e] = o;
    }
}

// ---------------------------------------------------------------------------
// K4: proj GEMM out = pre @ Wproj^T + b.  128x128x32 tile, 256 threads,
// 8x8 per thread (f32x2 over cols); B rows padded to 132 floats (528B=33*16).
// ---------------------------------------------------------------------------
#define BM4 128
#define BN4 128
#define BK4 32

__global__ __launch_bounds__(256)
void k_proj(const float* __restrict__ wp,
            const float* __restrict__ bias,
            float* __restrict__ out) {
    __shared__ float As[BM4][BK4+1];
    __shared__ __align__(16) float Bs[BK4][BN4+4];

    const int tid = threadIdx.x;
    const int tx = tid & 15;       // cols tx*8..+7
    const int ty = tid >> 4;       // rows ty*8..+7
    const int m0 = blockIdx.y * BM4;
    const int n0 = blockIdx.x * BN4;

    u64 acc[8][4];
    #pragma unroll
    for (int i = 0; i < 8; i++)
        #pragma unroll
        for (int j = 0; j < 4; j++) acc[i][j] = 0ull;

    for (int k0 = 0; k0 < CH; k0 += BK4) {
        #pragma unroll
        for (int l = tid; l < BM4*BK4; l += 256) {
            int r = l >> 5, c = l & 31;
            As[r][c] = g_pre[(size_t)(m0 + r)*CH + k0 + c];
        }
        #pragma unroll
        for (int l = tid; l < BN4*BK4; l += 256) {
            int r = l >> 5, c = l & 31;
            Bs[c][r] = wp[(size_t)(n0 + r)*CH + k0 + c];
        }
        __syncthreads();

        #pragma unroll
        for (int kk = 0; kk < BK4; kk++) {
            float a[8];
            #pragma unroll
            for (int i = 0; i < 8; i++) a[i] = As[ty*8 + i][kk];
            ulonglong2 b0 = *(const ulonglong2*)&Bs[kk][tx*8];
            ulonglong2 b1 = *(const ulonglong2*)&Bs[kk][tx*8 + 4];
            #pragma unroll
            for (int i = 0; i < 8; i++) {
                u64 ap = pk2(a[i], a[i]);
                acc[i][0] = ffma2(ap, b0.x, acc[i][0]);
                acc[i][1] = ffma2(ap, b0.y, acc[i][1]);
                acc[i][2] = ffma2(ap, b1.x, acc[i][2]);
                acc[i][3] = ffma2(ap, b1.y, acc[i][3]);
            }
        }
        __syncthreads();
    }

    #pragma unroll
    for (int i = 0; i < 8; i++) {
        int m = m0 + ty*8 + i;
        #pragma unroll
        for (int j = 0; j < 4; j++) {
            int col = n0 + tx*8 + j*2;
            float lo, hi;
            upk2(acc[i][j], lo, hi);
            out[(size_t)m*CH + col]     = lo + bias[col];
            out[(size_t)m*CH + col + 1] = hi + bias[col + 1];
        }
    }
}

// ---------------------------------------------------------------------------
extern "C" void kernel_launch(void* const* d_in, const int* in_sizes, int n_in,
                              void* d_out, int out_size) {
    const float* x = nullptr;
    const float* w[3] = {nullptr, nullptr, nullptr};   // w_qk, w_v, w_proj in order
    const float* bproj = nullptr;
    const float* dcw = nullptr;
    int wi = 0;
    for (int i = 0; i < n_in; i++) {
        int sz = in_sizes[i];
        if (sz == TOK*CH)            x = (const float*)d_in[i];
        else if (sz == CH*CH)        { if (wi < 3) w[wi++] = (const float*)d_in[i]; }
        else if (sz == CH)           bproj = (const float*)d_in[i];
        else if (sz == NH*KS9)       dcw = (const float*)d_in[i];
    }

    k_zero_attn<<<(BATCH*NH*HD*HD + 255)/256, 256>>>();
    k_qkv <<<dim3(CH/BN1, TOK/BM1), 256>>>(x, w[0], w[1]);
    k_attn<<<dim3(BATCH*NH, 8), 256>>>();
    k_out <<<dim3(BATCH*NH, SEQ/64), 384>>>(dcw);
    k_proj<<<dim3(CH/BN4, TOK/BM4), 256>>>(w[2], bproj, (float*)d_out);
}